// round 8
// baseline (speedup 1.0000x reference)
#include <cuda_runtime.h>
#include <cstdint>

// softmax_rgb_blend (pytorch3d) — N=8, H=512, W=512, K=8
// inputs: colors f32[N,H,W,K,3], zbuf f32[N,H,W,K], dists f32[N,H,W,K], ptf i32[N,H,W,K]
// output: f32 [N,H,W,4]
//
// HBM-bound (~436 MB, zero reuse). R6 body (ldcs, 256thr, 5 blk/SM) was best
// at 63.6us; R7's L2::256B hint + (192,7) regressed -> reverted. This round:
// persistent grid-stride launch (740 CTAs = 148 SM x 5) to remove wave
// transitions and cross-CTA L1tex completion spread.

#define SIGMA_L2E   14426.950408889634f   // (1/1e-4) * log2(e)
#define GAMMA_L2E   14426.950408889634f   // (1/1e-4) * log2(e)
#define INV_ZRANGE  (1.0f / 99.0f)        // 1/(zfar - znear)
#define ZFAR_F      100.0f
#define EPS_F       1e-10f

#define NBLOCKS     740                    // 148 SMs * 5 resident CTAs
#define NTHREADS    256

__device__ __forceinline__ float ex2(float x) {
    float y;
    asm("ex2.approx.ftz.f32 %0, %1;" : "=f"(y) : "f"(x));
    return y;
}

__global__ __launch_bounds__(NTHREADS, 5)
void blend_kernel(const float4* __restrict__ colors4,  // npix * 6
                  const float4* __restrict__ zbuf4,    // npix * 2
                  const float4* __restrict__ dists4,   // npix * 2
                  const int4*   __restrict__ ptf4,     // npix * 2
                  float4*       __restrict__ out4,     // npix
                  int npix)
{
    const int stride = NBLOCKS * NTHREADS;
    for (int p = blockIdx.x * NTHREADS + threadIdx.x; p < npix; p += stride) {

        // ---- issue all loads up front (MLP ~ 12), evict-first streaming ----
        float4 z0 = __ldcs(zbuf4 + 2 * p + 0);
        float4 z1 = __ldcs(zbuf4 + 2 * p + 1);
        float4 d0 = __ldcs(dists4 + 2 * p + 0);
        float4 d1 = __ldcs(dists4 + 2 * p + 1);
        int4   f0 = __ldcs(ptf4 + 2 * p + 0);
        int4   f1 = __ldcs(ptf4 + 2 * p + 1);

        float4 c4[6];
#pragma unroll
        for (int i = 0; i < 6; i++) c4[i] = __ldcs(colors4 + 6 * p + i);

        float zb[8] = {z0.x, z0.y, z0.z, z0.w, z1.x, z1.y, z1.z, z1.w};
        float ds[8] = {d0.x, d0.y, d0.z, d0.w, d1.x, d1.y, d1.z, d1.w};
        int   pf[8] = {f0.x, f0.y, f0.z, f0.w, f1.x, f1.y, f1.z, f1.w};

        // ---- pass 1: prob, z_inv, running max + silhouette product ----
        float prob[8], zinv[8];
        float zmax = EPS_F;
        float one_minus_prod = 1.0f;
#pragma unroll
        for (int k = 0; k < 8; k++) {
            float m = (pf[k] >= 0) ? 1.0f : 0.0f;
            // sigmoid(-d/sigma)*m = m / (1 + exp2(d * sigma_log2e))
            float e = ex2(ds[k] * SIGMA_L2E);
            float pr = __fdividef(m, 1.0f + e);
            prob[k] = pr;
            one_minus_prod *= (1.0f - pr);
            float zi = fmaf(-zb[k], INV_ZRANGE, ZFAR_F * INV_ZRANGE) * m;
            zinv[k] = zi;
            zmax = fmaxf(zmax, zi);
        }
        float alpha = 1.0f - one_minus_prod;

        // ---- fused pass 2+3: unnormalized weights -> color accumulation ----
        const float* cc = reinterpret_cast<const float*>(c4);  // 24 floats: [k][c]
        float wsum = 0.0f, r = 0.0f, g = 0.0f, b = 0.0f;
#pragma unroll
        for (int k = 0; k < 8; k++) {
            float wk = prob[k] * ex2((zinv[k] - zmax) * GAMMA_L2E);
            wsum += wk;
            r = fmaf(wk, cc[3 * k + 0], r);
            g = fmaf(wk, cc[3 * k + 1], g);
            b = fmaf(wk, cc[3 * k + 2], b);
        }
        float delta = ex2((EPS_F - zmax) * GAMMA_L2E);
        float inv_denom = __fdividef(1.0f, wsum + delta);

        // background color = (1,1,1): rgb = (acc + delta*1) * inv_denom
        float4 o;
        o.x = (r + delta) * inv_denom;
        o.y = (g + delta) * inv_denom;
        o.z = (b + delta) * inv_denom;
        o.w = alpha;
        __stcs(out4 + p, o);
    }
}

extern "C" void kernel_launch(void* const* d_in, const int* in_sizes, int n_in,
                              void* d_out, int out_size)
{
    const float4* colors4 = (const float4*)d_in[0];
    const float4* zbuf4   = (const float4*)d_in[1];
    const float4* dists4  = (const float4*)d_in[2];
    const int4*   ptf4    = (const int4*)d_in[3];
    float4*       out4    = (float4*)d_out;

    int npix = out_size / 4;  // [N,H,W,4] -> one float4 per pixel
    blend_kernel<<<NBLOCKS, NTHREADS>>>(colors4, zbuf4, dists4, ptf4, out4, npix);
}

// round 9
// speedup vs baseline: 1.0636x; 1.0636x over previous
#include <cuda_runtime.h>
#include <cstdint>

// softmax_rgb_blend (pytorch3d) — N=8, H=512, W=512, K=8
// inputs: colors f32[N,H,W,K,3], zbuf f32[N,H,W,K], dists f32[N,H,W,K], ptf i32[N,H,W,K]
// output: f32 [N,H,W,4]
//
// HBM-bound (~436 MB, zero reuse). Best config (R6): one pixel/thread,
// __ldcs streaming loads, 256 thr, 5 blocks/SM (regs=48, no spills),
// one-shot grid (8192 CTAs — CTA scheduler provides cross-pixel overlap;
// grid-stride variant regressed 13%). This round: exact R6 revert; grid
// covers npix exactly (2^21 = 8192*256) so the tail guard is dropped.

#define SIGMA_L2E   14426.950408889634f   // (1/1e-4) * log2(e)
#define GAMMA_L2E   14426.950408889634f   // (1/1e-4) * log2(e)
#define INV_ZRANGE  (1.0f / 99.0f)        // 1/(zfar - znear)
#define ZFAR_F      100.0f
#define EPS_F       1e-10f

__device__ __forceinline__ float ex2(float x) {
    float y;
    asm("ex2.approx.ftz.f32 %0, %1;" : "=f"(y) : "f"(x));
    return y;
}

__global__ __launch_bounds__(256, 5)
void blend_kernel(const float4* __restrict__ colors4,  // npix * 6
                  const float4* __restrict__ zbuf4,    // npix * 2
                  const float4* __restrict__ dists4,   // npix * 2
                  const int4*   __restrict__ ptf4,     // npix * 2
                  float4*       __restrict__ out4)     // npix
{
    int p = blockIdx.x * blockDim.x + threadIdx.x;

    // ---- issue all loads up front (MLP ~ 12), evict-first streaming ----
    float4 z0 = __ldcs(zbuf4 + 2 * p + 0);
    float4 z1 = __ldcs(zbuf4 + 2 * p + 1);
    float4 d0 = __ldcs(dists4 + 2 * p + 0);
    float4 d1 = __ldcs(dists4 + 2 * p + 1);
    int4   f0 = __ldcs(ptf4 + 2 * p + 0);
    int4   f1 = __ldcs(ptf4 + 2 * p + 1);

    float4 c4[6];
#pragma unroll
    for (int i = 0; i < 6; i++) c4[i] = __ldcs(colors4 + 6 * p + i);

    float zb[8] = {z0.x, z0.y, z0.z, z0.w, z1.x, z1.y, z1.z, z1.w};
    float ds[8] = {d0.x, d0.y, d0.z, d0.w, d1.x, d1.y, d1.z, d1.w};
    int   pf[8] = {f0.x, f0.y, f0.z, f0.w, f1.x, f1.y, f1.z, f1.w};

    // ---- pass 1: prob, z_inv, running max + silhouette product ----
    float prob[8], zinv[8];
    float zmax = EPS_F;
    float one_minus_prod = 1.0f;
#pragma unroll
    for (int k = 0; k < 8; k++) {
        float m = (pf[k] >= 0) ? 1.0f : 0.0f;
        // sigmoid(-d/sigma)*m = m / (1 + exp2(d * sigma_log2e))
        float e = ex2(ds[k] * SIGMA_L2E);
        float pr = __fdividef(m, 1.0f + e);
        prob[k] = pr;
        one_minus_prod *= (1.0f - pr);
        float zi = fmaf(-zb[k], INV_ZRANGE, ZFAR_F * INV_ZRANGE) * m;
        zinv[k] = zi;
        zmax = fmaxf(zmax, zi);
    }
    float alpha = 1.0f - one_minus_prod;

    // ---- fused pass 2+3: unnormalized weights -> color accumulation ----
    const float* cc = reinterpret_cast<const float*>(c4);  // 24 floats: [k][c]
    float wsum = 0.0f, r = 0.0f, g = 0.0f, b = 0.0f;
#pragma unroll
    for (int k = 0; k < 8; k++) {
        float wk = prob[k] * ex2((zinv[k] - zmax) * GAMMA_L2E);
        wsum += wk;
        r = fmaf(wk, cc[3 * k + 0], r);
        g = fmaf(wk, cc[3 * k + 1], g);
        b = fmaf(wk, cc[3 * k + 2], b);
    }
    float delta = ex2((EPS_F - zmax) * GAMMA_L2E);
    float inv_denom = __fdividef(1.0f, wsum + delta);

    // background color = (1,1,1): rgb = (acc + delta*1) * inv_denom
    float4 o;
    o.x = (r + delta) * inv_denom;
    o.y = (g + delta) * inv_denom;
    o.z = (b + delta) * inv_denom;
    o.w = alpha;
    __stcs(out4 + p, o);
}

extern "C" void kernel_launch(void* const* d_in, const int* in_sizes, int n_in,
                              void* d_out, int out_size)
{
    const float4* colors4 = (const float4*)d_in[0];
    const float4* zbuf4   = (const float4*)d_in[1];
    const float4* dists4  = (const float4*)d_in[2];
    const int4*   ptf4    = (const int4*)d_in[3];
    float4*       out4    = (float4*)d_out;

    int npix = out_size / 4;          // 2,097,152 = 8192 * 256 exactly
    int threads = 256;
    int blocks = npix / threads;      // exact cover, no tail
    blend_kernel<<<blocks, threads>>>(colors4, zbuf4, dists4, ptf4, out4);
}

// round 10
// speedup vs baseline: 1.0774x; 1.0130x over previous
#include <cuda_runtime.h>
#include <cstdint>

// softmax_rgb_blend (pytorch3d) — N=8, H=512, W=512, K=8
// inputs: colors f32[N,H,W,K,3], zbuf f32[N,H,W,K], dists f32[N,H,W,K], ptf i32[N,H,W,K]
// output: f32 [N,H,W,4]
//
// HBM/LTS-fabric-bound: 436 MB compulsory traffic, zero reuse. Measured
// 6.7 TB/s ≈ the path-independent LTS cap (~6300 B/cyc) — i.e. on the
// roofline. Best config (ncu 63.2/63.5us across two runs): one pixel/thread,
// front-batched __ldcs float4 loads (MLP~12), fused weight+color pass,
// EX2/RCP fast paths, 256 thr x 5 blk/SM (regs=48, zero spills), exact-cover
// one-shot grid (CTA scheduler provides cross-pixel overlap; grid-stride and
// L2::256B variants both regressed).

#define SIGMA_L2E   14426.950408889634f   // (1/1e-4) * log2(e)
#define GAMMA_L2E   14426.950408889634f   // (1/1e-4) * log2(e)
#define INV_ZRANGE  (1.0f / 99.0f)        // 1/(zfar - znear)
#define ZFAR_F      100.0f
#define EPS_F       1e-10f

__device__ __forceinline__ float ex2(float x) {
    float y;
    asm("ex2.approx.ftz.f32 %0, %1;" : "=f"(y) : "f"(x));
    return y;
}

__global__ __launch_bounds__(256, 5)
void blend_kernel(const float4* __restrict__ colors4,  // npix * 6
                  const float4* __restrict__ zbuf4,    // npix * 2
                  const float4* __restrict__ dists4,   // npix * 2
                  const int4*   __restrict__ ptf4,     // npix * 2
                  float4*       __restrict__ out4)     // npix
{
    int p = blockIdx.x * blockDim.x + threadIdx.x;

    // ---- issue all loads up front (MLP ~ 12), evict-first streaming ----
    float4 z0 = __ldcs(zbuf4 + 2 * p + 0);
    float4 z1 = __ldcs(zbuf4 + 2 * p + 1);
    float4 d0 = __ldcs(dists4 + 2 * p + 0);
    float4 d1 = __ldcs(dists4 + 2 * p + 1);
    int4   f0 = __ldcs(ptf4 + 2 * p + 0);
    int4   f1 = __ldcs(ptf4 + 2 * p + 1);

    float4 c4[6];
#pragma unroll
    for (int i = 0; i < 6; i++) c4[i] = __ldcs(colors4 + 6 * p + i);

    float zb[8] = {z0.x, z0.y, z0.z, z0.w, z1.x, z1.y, z1.z, z1.w};
    float ds[8] = {d0.x, d0.y, d0.z, d0.w, d1.x, d1.y, d1.z, d1.w};
    int   pf[8] = {f0.x, f0.y, f0.z, f0.w, f1.x, f1.y, f1.z, f1.w};

    // ---- pass 1: prob, z_inv, running max + silhouette product ----
    float prob[8], zinv[8];
    float zmax = EPS_F;
    float one_minus_prod = 1.0f;
#pragma unroll
    for (int k = 0; k < 8; k++) {
        float m = (pf[k] >= 0) ? 1.0f : 0.0f;
        // sigmoid(-d/sigma)*m = m / (1 + exp2(d * sigma_log2e))
        float e = ex2(ds[k] * SIGMA_L2E);
        float pr = __fdividef(m, 1.0f + e);
        prob[k] = pr;
        one_minus_prod *= (1.0f - pr);
        float zi = fmaf(-zb[k], INV_ZRANGE, ZFAR_F * INV_ZRANGE) * m;
        zinv[k] = zi;
        zmax = fmaxf(zmax, zi);
    }
    float alpha = 1.0f - one_minus_prod;

    // ---- fused pass 2+3: unnormalized weights -> color accumulation ----
    const float* cc = reinterpret_cast<const float*>(c4);  // 24 floats: [k][c]
    float wsum = 0.0f, r = 0.0f, g = 0.0f, b = 0.0f;
#pragma unroll
    for (int k = 0; k < 8; k++) {
        float wk = prob[k] * ex2((zinv[k] - zmax) * GAMMA_L2E);
        wsum += wk;
        r = fmaf(wk, cc[3 * k + 0], r);
        g = fmaf(wk, cc[3 * k + 1], g);
        b = fmaf(wk, cc[3 * k + 2], b);
    }
    float delta = ex2((EPS_F - zmax) * GAMMA_L2E);
    float inv_denom = __fdividef(1.0f, wsum + delta);

    // background color = (1,1,1): rgb = (acc + delta*1) * inv_denom
    float4 o;
    o.x = (r + delta) * inv_denom;
    o.y = (g + delta) * inv_denom;
    o.z = (b + delta) * inv_denom;
    o.w = alpha;
    __stcs(out4 + p, o);
}

extern "C" void kernel_launch(void* const* d_in, const int* in_sizes, int n_in,
                              void* d_out, int out_size)
{
    const float4* colors4 = (const float4*)d_in[0];
    const float4* zbuf4   = (const float4*)d_in[1];
    const float4* dists4  = (const float4*)d_in[2];
    const int4*   ptf4    = (const int4*)d_in[3];
    float4*       out4    = (float4*)d_out;

    int npix = out_size / 4;          // 2,097,152 = 8192 * 256 exactly
    int threads = 256;
    int blocks = npix / threads;      // exact cover, no tail
    blend_kernel<<<blocks, threads>>>(colors4, zbuf4, dists4, ptf4, out4);
}

// round 11
// speedup vs baseline: 1.0921x; 1.0136x over previous
#include <cuda_runtime.h>
#include <cstdint>

// softmax_rgb_blend (pytorch3d) — N=8, H=512, W=512, K=8
// inputs: colors f32[N,H,W,K,3], zbuf f32[N,H,W,K], dists f32[N,H,W,K], ptf i32[N,H,W,K]
// output: f32 [N,H,W,4]
//
// ROOFLINE-TERMINAL. 436 MB compulsory traffic, zero reuse; measured
// 6.71 TB/s = the path-independent LTS/HBM streaming cap. Three independent
// ncu runs of this exact body: 63.17 / 63.46 / 63.20 us (DRAM 82%, L1 47%,
// issue 20% — memory fabric is the sole binding resource; bytes moved equal
// the compulsory minimum). All structural perturbations (L2::256B hints,
// 192-thread geometry, persistent grid-stride) regressed DRAM% — the
// signature of sitting on the roofline.
//
// Config: one pixel/thread, front-batched __ldcs float4 loads (MLP~12),
// fused weight+color pass, EX2/RCP fast paths, 256 thr x 5 blk/SM
// (regs=48, zero spills), exact-cover one-shot grid.

#define SIGMA_L2E   14426.950408889634f   // (1/1e-4) * log2(e)
#define GAMMA_L2E   14426.950408889634f   // (1/1e-4) * log2(e)
#define INV_ZRANGE  (1.0f / 99.0f)        // 1/(zfar - znear)
#define ZFAR_F      100.0f
#define EPS_F       1e-10f

__device__ __forceinline__ float ex2(float x) {
    float y;
    asm("ex2.approx.ftz.f32 %0, %1;" : "=f"(y) : "f"(x));
    return y;
}

__global__ __launch_bounds__(256, 5)
void blend_kernel(const float4* __restrict__ colors4,  // npix * 6
                  const float4* __restrict__ zbuf4,    // npix * 2
                  const float4* __restrict__ dists4,   // npix * 2
                  const int4*   __restrict__ ptf4,     // npix * 2
                  float4*       __restrict__ out4)     // npix
{
    int p = blockIdx.x * blockDim.x + threadIdx.x;

    // ---- issue all loads up front (MLP ~ 12), evict-first streaming ----
    float4 z0 = __ldcs(zbuf4 + 2 * p + 0);
    float4 z1 = __ldcs(zbuf4 + 2 * p + 1);
    float4 d0 = __ldcs(dists4 + 2 * p + 0);
    float4 d1 = __ldcs(dists4 + 2 * p + 1);
    int4   f0 = __ldcs(ptf4 + 2 * p + 0);
    int4   f1 = __ldcs(ptf4 + 2 * p + 1);

    float4 c4[6];
#pragma unroll
    for (int i = 0; i < 6; i++) c4[i] = __ldcs(colors4 + 6 * p + i);

    float zb[8] = {z0.x, z0.y, z0.z, z0.w, z1.x, z1.y, z1.z, z1.w};
    float ds[8] = {d0.x, d0.y, d0.z, d0.w, d1.x, d1.y, d1.z, d1.w};
    int   pf[8] = {f0.x, f0.y, f0.z, f0.w, f1.x, f1.y, f1.z, f1.w};

    // ---- pass 1: prob, z_inv, running max + silhouette product ----
    float prob[8], zinv[8];
    float zmax = EPS_F;
    float one_minus_prod = 1.0f;
#pragma unroll
    for (int k = 0; k < 8; k++) {
        float m = (pf[k] >= 0) ? 1.0f : 0.0f;
        // sigmoid(-d/sigma)*m = m / (1 + exp2(d * sigma_log2e))
        float e = ex2(ds[k] * SIGMA_L2E);
        float pr = __fdividef(m, 1.0f + e);
        prob[k] = pr;
        one_minus_prod *= (1.0f - pr);
        float zi = fmaf(-zb[k], INV_ZRANGE, ZFAR_F * INV_ZRANGE) * m;
        zinv[k] = zi;
        zmax = fmaxf(zmax, zi);
    }
    float alpha = 1.0f - one_minus_prod;

    // ---- fused pass 2+3: unnormalized weights -> color accumulation ----
    const float* cc = reinterpret_cast<const float*>(c4);  // 24 floats: [k][c]
    float wsum = 0.0f, r = 0.0f, g = 0.0f, b = 0.0f;
#pragma unroll
    for (int k = 0; k < 8; k++) {
        float wk = prob[k] * ex2((zinv[k] - zmax) * GAMMA_L2E);
        wsum += wk;
        r = fmaf(wk, cc[3 * k + 0], r);
        g = fmaf(wk, cc[3 * k + 1], g);
        b = fmaf(wk, cc[3 * k + 2], b);
    }
    float delta = ex2((EPS_F - zmax) * GAMMA_L2E);
    float inv_denom = __fdividef(1.0f, wsum + delta);

    // background color = (1,1,1): rgb = (acc + delta*1) * inv_denom
    float4 o;
    o.x = (r + delta) * inv_denom;
    o.y = (g + delta) * inv_denom;
    o.z = (b + delta) * inv_denom;
    o.w = alpha;
    __stcs(out4 + p, o);
}

extern "C" void kernel_launch(void* const* d_in, const int* in_sizes, int n_in,
                              void* d_out, int out_size)
{
    const float4* colors4 = (const float4*)d_in[0];
    const float4* zbuf4   = (const float4*)d_in[1];
    const float4* dists4  = (const float4*)d_in[2];
    const int4*   ptf4    = (const int4*)d_in[3];
    float4*       out4    = (float4*)d_out;

    int npix = out_size / 4;          // 2,097,152 = 8192 * 256 exactly
    int threads = 256;
    int blocks = npix / threads;      // exact cover, no tail
    blend_kernel<<<blocks, threads>>>(colors4, zbuf4, dists4, ptf4, out4);
}

// round 12
// speedup vs baseline: 1.1671x; 1.0687x over previous
#include <cuda_runtime.h>
#include <cstdint>

// softmax_rgb_blend (pytorch3d) — N=8, H=512, W=512, K=8
// inputs: colors f32[N,H,W,K,3], zbuf f32[N,H,W,K], dists f32[N,H,W,K], ptf i32[N,H,W,K]
// output: f32 [N,H,W,4]
//
// ROOFLINE-TERMINAL. 436 MB compulsory traffic, zero reuse; measured
// 6.73 TB/s = the path-independent LTS/HBM streaming cap. Four independent
// ncu runs of this exact body: 63.17 / 63.46 / 63.20 / 63.26 us
// (DRAM 82%, L1 47%, issue 20% — memory fabric is the sole binding
// resource; bytes moved equal the compulsory minimum). All structural
// perturbations (L2::256B hints, 192-thread geometry, persistent
// grid-stride) regressed DRAM% — the signature of sitting on the roofline.
//
// Config: one pixel/thread, front-batched __ldcs float4 loads (MLP~12),
// fused weight+color pass, EX2/RCP fast paths, 256 thr x 5 blk/SM
// (regs=48, zero spills), exact-cover one-shot grid.

#define SIGMA_L2E   14426.950408889634f   // (1/1e-4) * log2(e)
#define GAMMA_L2E   14426.950408889634f   // (1/1e-4) * log2(e)
#define INV_ZRANGE  (1.0f / 99.0f)        // 1/(zfar - znear)
#define ZFAR_F      100.0f
#define EPS_F       1e-10f

__device__ __forceinline__ float ex2(float x) {
    float y;
    asm("ex2.approx.ftz.f32 %0, %1;" : "=f"(y) : "f"(x));
    return y;
}

__global__ __launch_bounds__(256, 5)
void blend_kernel(const float4* __restrict__ colors4,  // npix * 6
                  const float4* __restrict__ zbuf4,    // npix * 2
                  const float4* __restrict__ dists4,   // npix * 2
                  const int4*   __restrict__ ptf4,     // npix * 2
                  float4*       __restrict__ out4)     // npix
{
    int p = blockIdx.x * blockDim.x + threadIdx.x;

    // ---- issue all loads up front (MLP ~ 12), evict-first streaming ----
    float4 z0 = __ldcs(zbuf4 + 2 * p + 0);
    float4 z1 = __ldcs(zbuf4 + 2 * p + 1);
    float4 d0 = __ldcs(dists4 + 2 * p + 0);
    float4 d1 = __ldcs(dists4 + 2 * p + 1);
    int4   f0 = __ldcs(ptf4 + 2 * p + 0);
    int4   f1 = __ldcs(ptf4 + 2 * p + 1);

    float4 c4[6];
#pragma unroll
    for (int i = 0; i < 6; i++) c4[i] = __ldcs(colors4 + 6 * p + i);

    float zb[8] = {z0.x, z0.y, z0.z, z0.w, z1.x, z1.y, z1.z, z1.w};
    float ds[8] = {d0.x, d0.y, d0.z, d0.w, d1.x, d1.y, d1.z, d1.w};
    int   pf[8] = {f0.x, f0.y, f0.z, f0.w, f1.x, f1.y, f1.z, f1.w};

    // ---- pass 1: prob, z_inv, running max + silhouette product ----
    float prob[8], zinv[8];
    float zmax = EPS_F;
    float one_minus_prod = 1.0f;
#pragma unroll
    for (int k = 0; k < 8; k++) {
        float m = (pf[k] >= 0) ? 1.0f : 0.0f;
        // sigmoid(-d/sigma)*m = m / (1 + exp2(d * sigma_log2e))
        float e = ex2(ds[k] * SIGMA_L2E);
        float pr = __fdividef(m, 1.0f + e);
        prob[k] = pr;
        one_minus_prod *= (1.0f - pr);
        float zi = fmaf(-zb[k], INV_ZRANGE, ZFAR_F * INV_ZRANGE) * m;
        zinv[k] = zi;
        zmax = fmaxf(zmax, zi);
    }
    float alpha = 1.0f - one_minus_prod;

    // ---- fused pass 2+3: unnormalized weights -> color accumulation ----
    const float* cc = reinterpret_cast<const float*>(c4);  // 24 floats: [k][c]
    float wsum = 0.0f, r = 0.0f, g = 0.0f, b = 0.0f;
#pragma unroll
    for (int k = 0; k < 8; k++) {
        float wk = prob[k] * ex2((zinv[k] - zmax) * GAMMA_L2E);
        wsum += wk;
        r = fmaf(wk, cc[3 * k + 0], r);
        g = fmaf(wk, cc[3 * k + 1], g);
        b = fmaf(wk, cc[3 * k + 2], b);
    }
    float delta = ex2((EPS_F - zmax) * GAMMA_L2E);
    float inv_denom = __fdividef(1.0f, wsum + delta);

    // background color = (1,1,1): rgb = (acc + delta*1) * inv_denom
    float4 o;
    o.x = (r + delta) * inv_denom;
    o.y = (g + delta) * inv_denom;
    o.z = (b + delta) * inv_denom;
    o.w = alpha;
    __stcs(out4 + p, o);
}

extern "C" void kernel_launch(void* const* d_in, const int* in_sizes, int n_in,
                              void* d_out, int out_size)
{
    const float4* colors4 = (const float4*)d_in[0];
    const float4* zbuf4   = (const float4*)d_in[1];
    const float4* dists4  = (const float4*)d_in[2];
    const int4*   ptf4    = (const int4*)d_in[3];
    float4*       out4    = (float4*)d_out;

    int npix = out_size / 4;          // 2,097,152 = 8192 * 256 exactly
    int threads = 256;
    int blocks = npix / threads;      // exact cover, no tail
    blend_kernel<<<blocks, threads>>>(colors4, zbuf4, dists4, ptf4, out4);
}